// round 2
// baseline (speedup 1.0000x reference)
#include <cuda_runtime.h>
#include <math.h>
#include <float.h>

#define D 256
#define MAX_N 500000
#define MAX_S 20000
#define NPB 512   // nodes per block in pooled pass
#define CH  128   // smem staging chunk
#define TM  64    // rows per block in epilogue GEMM

// Scratch (static device globals — no allocation)
__device__ float g_gate[MAX_N];
__device__ float g_segmax[MAX_S];
__device__ float g_denom[MAX_S];
__device__ float g_pooled[(size_t)MAX_S * D];

__device__ __forceinline__ void atomicMaxFloat(float* addr, float val) {
    int* ai = (int*)addr;
    int old = *ai;
    while (__int_as_float(old) < val) {
        int assumed = old;
        old = atomicCAS(ai, assumed, __float_as_int(val));
        if (old == assumed) break;
    }
}

__global__ void init_kernel(int S) {
    int i = blockIdx.x * blockDim.x + threadIdx.x;
    if (i < S * D) g_pooled[i] = 0.f;
    if (i < S) { g_segmax[i] = -FLT_MAX; g_denom[i] = 0.f; }
}

// Pass 1: gate logits (x . Wg + bg) + per-segment max. One node per warp.
__global__ void gate_kernel(const float* __restrict__ x, const float* __restrict__ Wg,
                            const float* __restrict__ bg, const int* __restrict__ index,
                            int N) {
    __shared__ float4 wg_s[D / 4];
    int tid = threadIdx.x;
    if (tid < D / 4) wg_s[tid] = ((const float4*)Wg)[tid];
    __syncthreads();
    int lane = tid & 31;
    int warp = (blockIdx.x * blockDim.x + tid) >> 5;
    int nwarps = (gridDim.x * blockDim.x) >> 5;
    float b = bg[0];
    for (int n = warp; n < N; n += nwarps) {
        const float4* xr = (const float4*)(x + (size_t)n * D);
        float s = 0.f;
        #pragma unroll
        for (int i = 0; i < 2; i++) {
            float4 xv = xr[lane + 32 * i];
            float4 wv = wg_s[lane + 32 * i];
            s += xv.x * wv.x + xv.y * wv.y + xv.z * wv.z + xv.w * wv.w;
        }
        #pragma unroll
        for (int o = 16; o > 0; o >>= 1) s += __shfl_xor_sync(0xffffffffu, s, o);
        if (lane == 0) {
            float g = s + b;
            g_gate[n] = g;
            atomicMaxFloat(&g_segmax[index[n]], g);
        }
    }
}

// Pass 2: e = w^p * exp(g - segmax) ; denom += e
__global__ void exp_kernel(const float* __restrict__ weights, const float* __restrict__ p,
                           const int* __restrict__ index, int N) {
    int n = blockIdx.x * blockDim.x + threadIdx.x;
    if (n >= N) return;
    int s = index[n];
    // w^p * exp(d) == exp(p*log(w) + d), w > 0 guaranteed
    float e = expf(fmaf(p[0], logf(weights[n]), g_gate[n] - g_segmax[s]));
    g_gate[n] = e;
    atomicAdd(&g_denom[s], e);
}

// Pass 3: pooled[seg,:] += (e/(denom+eps)) * x[n,:]
// Thread t owns feature t. Sorted index -> register accumulation per segment,
// flush via atomicAdd on segment change (correct even if unsorted).
__global__ void pooled_kernel(const float* __restrict__ x, const int* __restrict__ index,
                              int N) {
    __shared__ float gate_s[CH];
    __shared__ int idx_s[CH];
    int tid = threadIdx.x;
    int base = blockIdx.x * NPB;
    float acc = 0.f;
    int cur = -1;
    for (int c0 = 0; c0 < NPB; c0 += CH) {
        int nb = min(CH, N - (base + c0));
        if (nb <= 0) break;
        if (tid < nb) {
            int n = base + c0 + tid;
            int sg = index[n];
            idx_s[tid] = sg;
            gate_s[tid] = g_gate[n] / (g_denom[sg] + 1e-10f);
        }
        __syncthreads();
        const float* xp = x + (size_t)(base + c0) * D + tid;
        for (int j = 0; j < nb; j++) {
            int sg = idx_s[j];
            if (sg != cur) {
                if (cur >= 0) atomicAdd(&g_pooled[(size_t)cur * D + tid], acc);
                acc = 0.f;
                cur = sg;
            }
            acc = fmaf(gate_s[j], xp[(size_t)j * D], acc);
        }
        __syncthreads();
    }
    if (cur >= 0) atomicAdd(&g_pooled[(size_t)cur * D + tid], acc);
}

// Pass 4: out = pooled @ Wm + (denom/(denom+eps)) * bm
// Block: TM rows x 256 cols; thread t owns column t, TM accumulators in regs.
__global__ void gemm_kernel(const float* __restrict__ Wm, const float* __restrict__ bm,
                            float* __restrict__ out, int S) {
    __shared__ float A[TM][32];
    int tid = threadIdx.x;
    int row0 = blockIdx.x * TM;
    float acc[TM];
    #pragma unroll
    for (int r = 0; r < TM; r++) acc[r] = 0.f;

    #pragma unroll 1
    for (int k0 = 0; k0 < D; k0 += 32) {
        #pragma unroll
        for (int i = 0; i < TM * 32 / 256; i++) {
            int idx = tid + i * 256;
            int r = idx >> 5, kk = idx & 31;
            int row = row0 + r;
            A[r][kk] = (row < S) ? g_pooled[(size_t)row * D + k0 + kk] : 0.f;
        }
        __syncthreads();
        #pragma unroll
        for (int kk = 0; kk < 32; kk++) {
            float bv = Wm[(size_t)(k0 + kk) * D + tid];
            #pragma unroll
            for (int r = 0; r < TM; r++)
                acc[r] = fmaf(A[r][kk], bv, acc[r]);
        }
        __syncthreads();
    }

    float bmv = bm[tid];
    #pragma unroll
    for (int r = 0; r < TM; r++) {
        int row = row0 + r;
        if (row < S) {
            float dn = g_denom[row];
            out[(size_t)row * D + tid] = acc[r] + (dn / (dn + 1e-10f)) * bmv;
        }
    }
}

extern "C" void kernel_launch(void* const* d_in, const int* in_sizes, int n_in,
                              void* d_out, int out_size) {
    const float* x       = (const float*)d_in[0];
    const float* weights = (const float*)d_in[1];
    const float* Wg      = (const float*)d_in[2];
    const float* bg      = (const float*)d_in[3];
    const float* Wm      = (const float*)d_in[4];
    const float* bm      = (const float*)d_in[5];
    const float* p       = (const float*)d_in[6];
    const int*   index   = (const int*)d_in[7];
    float* out = (float*)d_out;

    int N = in_sizes[7];          // number of nodes (== len(index))
    int S = out_size / D;         // number of segments

    init_kernel<<<(S * D + 255) / 256, 256>>>(S);
    gate_kernel<<<(N + 7) / 8, 256>>>(x, Wg, bg, index, N);   // 1 node/warp
    exp_kernel<<<(N + 255) / 256, 256>>>(weights, p, index, N);
    pooled_kernel<<<(N + NPB - 1) / NPB, 256>>>(x, index, N);
    gemm_kernel<<<(S + TM - 1) / TM, 256>>>(Wm, bm, out, S);
}

// round 4
// speedup vs baseline: 2.7957x; 2.7957x over previous
#include <cuda_runtime.h>
#include <math.h>
#include <float.h>

#define D 256
#define MAX_S 20000
#define SEGPB 8      // segments per block in fused kernel
#define CHK 128      // node chunk per segment pass
#define GTM 32       // rows per block in epilogue GEMM

// Scratch (static device globals — no allocation)
__device__ float g_pooled[(size_t)MAX_S * D];  // normalized: sum(gate_norm * x)
__device__ float g_sumg[MAX_S];                // sum(gate_norm) = d/(d+eps)
__device__ int   g_segstart[MAX_S + 1];

// --- Kernel 1: segment start offsets via binary search (index is sorted) ---
__global__ void segstart_kernel(const int* __restrict__ index, int N, int S) {
    int s = blockIdx.x * blockDim.x + threadIdx.x;
    if (s > S) return;
    if (s == S) { g_segstart[S] = N; return; }
    int lo = 0, hi = N;                       // lower_bound: first i with index[i] >= s
    while (lo < hi) { int mid = (lo + hi) >> 1; if (index[mid] < s) lo = mid + 1; else hi = mid; }
    g_segstart[s] = lo;
}

// --- Kernel 2: fused gate + softmax + weighted pooling, single x read ---
// Each block owns SEGPB whole segments. Per segment, chunked online softmax:
//   h = x.Wg + bg + p*ln(w);  e = exp(h - running_max);  pooled = sum(e*x)/(sum e + eps)
// The per-segment constant cancels in normalization -> identical to reference.
__global__ __launch_bounds__(256) void fused_kernel(
    const float* __restrict__ x, const float* __restrict__ weights,
    const float* __restrict__ Wg, const float* __restrict__ bg,
    const float* __restrict__ p, int S)
{
    __shared__ float4 wg4[D / 4];
    __shared__ float h_s[CHK];
    __shared__ float e_s[CHK];
    __shared__ float red[8];

    int tid = threadIdx.x, lane = tid & 31, wid = tid >> 5;
    if (tid < D / 4) wg4[tid] = ((const float4*)Wg)[tid];
    float bgv = bg[0], pv = p[0];
    __syncthreads();

    int s0 = blockIdx.x * SEGPB;
    int s1 = min(s0 + SEGPB, S);
    for (int s = s0; s < s1; s++) {
        int a = g_segstart[s], b = g_segstart[s + 1];
        float m = -FLT_MAX, d = 0.f, a0 = 0.f, a1 = 0.f;

        for (int c = a; c < b; c += CHK) {
            int cnt = min(CHK, b - c);

            // Stage 1: warp-per-node gate logits -> smem
            float wmax = -FLT_MAX;
            for (int j = wid; j < cnt; j += 8) {
                const float4* xr = (const float4*)(x + (size_t)(c + j) * D);
                float4 v1 = xr[lane], v2 = xr[lane + 32];
                float4 w1 = wg4[lane], w2 = wg4[lane + 32];
                float sd = v1.x * w1.x + v1.y * w1.y + v1.z * w1.z + v1.w * w1.w
                         + v2.x * w2.x + v2.y * w2.y + v2.z * w2.z + v2.w * w2.w;
                #pragma unroll
                for (int o = 16; o > 0; o >>= 1) sd += __shfl_xor_sync(0xffffffffu, sd, o);
                if (lane == 0) {
                    float hh = fmaf(pv, __logf(weights[c + j]), sd + bgv);
                    h_s[j] = hh;
                    wmax = fmaxf(wmax, hh);
                }
            }
            if (lane == 0) red[wid] = wmax;
            __syncthreads();

            // chunk max -> new running max, rescale carried accumulators
            float cm = red[0];
            #pragma unroll
            for (int i = 1; i < 8; i++) cm = fmaxf(cm, red[i]);
            float nm = fmaxf(m, cm);
            if (tid < cnt) e_s[tid] = __expf(h_s[tid] - nm);
            float r = __expf(m - nm);   // m = -FLT_MAX on first chunk -> r = 0, accs are 0
            a0 *= r; a1 *= r; d *= r;
            m = nm;
            __syncthreads();

            // Stage 2: thread-per-feature accumulation (x rows hot in L1/L2)
            const float* xp = x + (size_t)c * D + tid;
            int j = 0;
            #pragma unroll 4
            for (; j + 1 < cnt; j += 2) {
                float e0 = e_s[j], e1 = e_s[j + 1];
                a0 = fmaf(e0, xp[(size_t)j * D], a0);
                a1 = fmaf(e1, xp[(size_t)(j + 1) * D], a1);
                d += e0 + e1;
            }
            if (j < cnt) { float e0 = e_s[j]; a0 = fmaf(e0, xp[(size_t)j * D], a0); d += e0; }
            __syncthreads();
        }

        float inv = 1.f / (d + 1e-10f);
        g_pooled[(size_t)s * D + tid] = (a0 + a1) * inv;
        if (tid == 0) g_sumg[s] = d * inv;   // sum of normalized gates (empty seg -> 0)
    }
}

// --- Kernel 3: out = pooled_norm @ Wm + sumg * bm ---
// 256 threads = 256 output columns; GTM rows per block; A transposed in smem so
// the inner loop fetches 4 row-values per LDS.128 (broadcast, conflict-free).
__global__ __launch_bounds__(256) void gemm_kernel(
    const float* __restrict__ Wm, const float* __restrict__ bm,
    float* __restrict__ out, int S)
{
    __shared__ float As[32][GTM + 4];   // As[kk][r], pad keeps 16B alignment
    int tid = threadIdx.x;
    int row0 = blockIdx.x * GTM;

    float acc[GTM];
    #pragma unroll
    for (int r = 0; r < GTM; r++) acc[r] = 0.f;

    for (int k0 = 0; k0 < D; k0 += 32) {
        #pragma unroll
        for (int i = 0; i < GTM * 32 / 256; i++) {
            int idx = tid + i * 256;
            int r = idx >> 5, kk = idx & 31;
            int row = row0 + r;
            As[kk][r] = (row < S) ? g_pooled[(size_t)row * D + k0 + kk] : 0.f;
        }
        __syncthreads();
        #pragma unroll
        for (int kk = 0; kk < 32; kk++) {
            float bv = Wm[(size_t)(k0 + kk) * D + tid];
            #pragma unroll
            for (int r4 = 0; r4 < GTM; r4 += 4) {
                float4 av = *(const float4*)&As[kk][r4];
                acc[r4 + 0] = fmaf(av.x, bv, acc[r4 + 0]);
                acc[r4 + 1] = fmaf(av.y, bv, acc[r4 + 1]);
                acc[r4 + 2] = fmaf(av.z, bv, acc[r4 + 2]);
                acc[r4 + 3] = fmaf(av.w, bv, acc[r4 + 3]);
            }
        }
        __syncthreads();
    }

    float bmv = bm[tid];
    #pragma unroll
    for (int r = 0; r < GTM; r++) {
        int row = row0 + r;
        if (row < S)
            out[(size_t)row * D + tid] = acc[r] + g_sumg[row] * bmv;
    }
}

extern "C" void kernel_launch(void* const* d_in, const int* in_sizes, int n_in,
                              void* d_out, int out_size) {
    const float* x       = (const float*)d_in[0];
    const float* weights = (const float*)d_in[1];
    const float* Wg      = (const float*)d_in[2];
    const float* bg      = (const float*)d_in[3];
    const float* Wm      = (const float*)d_in[4];
    const float* bm      = (const float*)d_in[5];
    const float* p       = (const float*)d_in[6];
    const int*   index   = (const int*)d_in[7];
    float* out = (float*)d_out;

    int N = in_sizes[7];
    int S = out_size / D;

    segstart_kernel<<<(S + 1 + 255) / 256, 256>>>(index, N, S);
    fused_kernel<<<(S + SEGPB - 1) / SEGPB, 256>>>(x, weights, Wg, bg, p, S);
    gemm_kernel<<<(S + GTM - 1) / GTM, 256>>>(Wm, bm, out, S);
}

// round 7
// speedup vs baseline: 3.1874x; 1.1401x over previous
#include <cuda_runtime.h>
#include <math.h>
#include <float.h>

#define D 256
#define MAX_S 20000
#define GTM 32    // rows per block in epilogue GEMM

// Scratch (static device globals — no allocation)
__device__ float g_pooled[(size_t)MAX_S * D];  // normalized: sum(gate_norm * x)
__device__ float g_sumg[MAX_S];                // sum(gate_norm) = d/(d+eps)
__device__ int   g_segstart[MAX_S + 1];

// --- Kernel 1: segment boundaries by marking (index sorted, one coalesced pass) ---
__global__ void segstart_kernel(const int* __restrict__ index, int N, int S) {
    int i = blockIdx.x * blockDim.x + threadIdx.x;
    if (i >= N) return;
    int cur = index[i];
    int prev = (i == 0) ? -1 : index[i - 1];   // neighbor load: L1/L2 hit
    for (int s = prev + 1; s <= cur; s++) g_segstart[s] = i;
    if (i == N - 1)
        for (int s = cur + 1; s <= S; s++) g_segstart[s] = N;
}

// --- Kernel 2: fused gate + online softmax + weighted pooling ---
// One WARP per segment. Single pass over x: the row loaded for the gate dot
// product is reused (same registers) for the pooled accumulation. Online
// max-rescaling (flash-attention style) keeps it exact; the per-segment
// constant cancels in normalization -> matches reference softmax.
__global__ __launch_bounds__(256) void fused_kernel(
    const float* __restrict__ x, const float* __restrict__ weights,
    const float* __restrict__ Wg, const float* __restrict__ bg,
    const float* __restrict__ p, int S)
{
    int lane = threadIdx.x & 31;
    int seg = (blockIdx.x * blockDim.x + threadIdx.x) >> 5;
    if (seg >= S) return;

    const float4* wg4 = (const float4*)Wg;
    float4 w1 = wg4[lane], w2 = wg4[lane + 32];   // Wg resident in registers
    float bgv = bg[0], pv = p[0];

    int a = g_segstart[seg], b = g_segstart[seg + 1];

    float m = -FLT_MAX, d = 0.f;
    float4 A1 = make_float4(0.f, 0.f, 0.f, 0.f);
    float4 A2 = make_float4(0.f, 0.f, 0.f, 0.f);

    float4 v1, v2; float wn;
    if (a < b) {
        const float4* xr = (const float4*)(x + (size_t)a * D);
        v1 = xr[lane]; v2 = xr[lane + 32]; wn = weights[a];
    }

    for (int n = a; n < b; n++) {
        float4 c1 = v1, c2 = v2; float wc = wn;
        if (n + 1 < b) {   // prefetch next row while reducing current
            const float4* xn = (const float4*)(x + (size_t)(n + 1) * D);
            v1 = xn[lane]; v2 = xn[lane + 32]; wn = weights[n + 1];
        }
        float sd = c1.x * w1.x + c1.y * w1.y + c1.z * w1.z + c1.w * w1.w
                 + c2.x * w2.x + c2.y * w2.y + c2.z * w2.z + c2.w * w2.w;
        #pragma unroll
        for (int o = 16; o > 0; o >>= 1) sd += __shfl_xor_sync(0xffffffffu, sd, o);

        float h = fmaf(pv, __logf(wc), sd + bgv);
        if (h > m) {                      // warp-uniform, rare after warm-up
            float r = __expf(m - h);      // first node: exp(-inf) = 0
            m = h; d *= r;
            A1.x *= r; A1.y *= r; A1.z *= r; A1.w *= r;
            A2.x *= r; A2.y *= r; A2.z *= r; A2.w *= r;
        }
        float e = __expf(h - m);
        d += e;
        A1.x = fmaf(e, c1.x, A1.x); A1.y = fmaf(e, c1.y, A1.y);
        A1.z = fmaf(e, c1.z, A1.z); A1.w = fmaf(e, c1.w, A1.w);
        A2.x = fmaf(e, c2.x, A2.x); A2.y = fmaf(e, c2.y, A2.y);
        A2.z = fmaf(e, c2.z, A2.z); A2.w = fmaf(e, c2.w, A2.w);
    }

    float inv = 1.f / (d + 1e-10f);
    A1.x *= inv; A1.y *= inv; A1.z *= inv; A1.w *= inv;
    A2.x *= inv; A2.y *= inv; A2.z *= inv; A2.w *= inv;
    float4* po = (float4*)(g_pooled + (size_t)seg * D);
    po[lane] = A1; po[lane + 32] = A2;
    if (lane == 0) g_sumg[seg] = d * inv;   // empty segment -> 0
}

// --- Kernel 3: out = pooled_norm @ Wm + sumg * bm (unchanged, known good) ---
__global__ __launch_bounds__(256) void gemm_kernel(
    const float* __restrict__ Wm, const float* __restrict__ bm,
    float* __restrict__ out, int S)
{
    __shared__ float As[32][GTM + 4];
    int tid = threadIdx.x;
    int row0 = blockIdx.x * GTM;

    float acc[GTM];
    #pragma unroll
    for (int r = 0; r < GTM; r++) acc[r] = 0.f;

    for (int k0 = 0; k0 < D; k0 += 32) {
        #pragma unroll
        for (int i = 0; i < GTM * 32 / 256; i++) {
            int idx = tid + i * 256;
            int r = idx >> 5, kk = idx & 31;
            int row = row0 + r;
            As[kk][r] = (row < S) ? g_pooled[(size_t)row * D + k0 + kk] : 0.f;
        }
        __syncthreads();
        #pragma unroll
        for (int kk = 0; kk < 32; kk++) {
            float bv = Wm[(size_t)(k0 + kk) * D + tid];
            #pragma unroll
            for (int r4 = 0; r4 < GTM; r4 += 4) {
                float4 av = *(const float4*)&As[kk][r4];
                acc[r4 + 0] = fmaf(av.x, bv, acc[r4 + 0]);
                acc[r4 + 1] = fmaf(av.y, bv, acc[r4 + 1]);
                acc[r4 + 2] = fmaf(av.z, bv, acc[r4 + 2]);
                acc[r4 + 3] = fmaf(av.w, bv, acc[r4 + 3]);
            }
        }
        __syncthreads();
    }

    float bmv = bm[tid];
    #pragma unroll
    for (int r = 0; r < GTM; r++) {
        int row = row0 + r;
        if (row < S)
            out[(size_t)row * D + tid] = acc[r] + g_sumg[row] * bmv;
    }
}

extern "C" void kernel_launch(void* const* d_in, const int* in_sizes, int n_in,
                              void* d_out, int out_size) {
    const float* x       = (const float*)d_in[0];
    const float* weights = (const float*)d_in[1];
    const float* Wg      = (const float*)d_in[2];
    const float* bg      = (const float*)d_in[3];
    const float* Wm      = (const float*)d_in[4];
    const float* bm      = (const float*)d_in[5];
    const float* p       = (const float*)d_in[6];
    const int*   index   = (const int*)d_in[7];
    float* out = (float*)d_out;

    int N = in_sizes[7];
    int S = out_size / D;

    segstart_kernel<<<(N + 255) / 256, 256>>>(index, N, S);
    fused_kernel<<<(S * 32 + 255) / 256, 256>>>(x, weights, Wg, bg, p, S);
    gemm_kernel<<<(S + GTM - 1) / GTM, 256>>>(Wm, bm, out, S);
}

// round 8
// speedup vs baseline: 3.4166x; 1.0719x over previous
#include <cuda_runtime.h>
#include <math.h>
#include <float.h>

#define D 256
#define MAX_S 20000
#define GTM 64    // rows per block in epilogue GEMM

// Scratch (static device globals — no allocation)
__device__ float g_pooled[(size_t)MAX_S * D];  // normalized: sum(gate_norm * x)
__device__ float g_sumg[MAX_S];                // sum(gate_norm) = d/(d+eps)
__device__ int   g_segstart[MAX_S + 1];

// --- Kernel 1: segment boundaries by marking (index sorted, one coalesced pass) ---
__global__ void segstart_kernel(const int* __restrict__ index, int N, int S) {
    int i = blockIdx.x * blockDim.x + threadIdx.x;
    if (i >= N) return;
    int cur = index[i];
    int prev = (i == 0) ? -1 : index[i - 1];
    for (int s = prev + 1; s <= cur; s++) g_segstart[s] = i;
    if (i == N - 1)
        for (int s = cur + 1; s <= S; s++) g_segstart[s] = N;
}

// --- Kernel 2: fused gate + online softmax + weighted pooling ---
// One warp per segment, TWO nodes per iteration with interleaved shfl chains
// (halves the exposed shuffle-reduction latency) and pair-ahead prefetch.
__global__ __launch_bounds__(256) void fused_kernel(
    const float* __restrict__ x, const float* __restrict__ weights,
    const float* __restrict__ Wg, const float* __restrict__ bg,
    const float* __restrict__ p, int S)
{
    int lane = threadIdx.x & 31;
    int seg = (blockIdx.x * blockDim.x + threadIdx.x) >> 5;
    if (seg >= S) return;

    const float4* wg4 = (const float4*)Wg;
    float4 w1 = wg4[lane], w2 = wg4[lane + 32];
    float bgv = bg[0], pv = p[0];

    int a = g_segstart[seg], b = g_segstart[seg + 1];

    float m = -FLT_MAX, d = 0.f;
    float4 A1 = make_float4(0.f, 0.f, 0.f, 0.f);
    float4 A2 = make_float4(0.f, 0.f, 0.f, 0.f);

    float4 u0a, u0b, u1a, u1b; float q0, q1;
    if (a < b) {
        int n1 = (a + 1 < b) ? a + 1 : a;
        const float4* r0 = (const float4*)(x + (size_t)a * D);
        const float4* r1 = (const float4*)(x + (size_t)n1 * D);
        u0a = __ldcs(r0 + lane); u0b = __ldcs(r0 + lane + 32);
        u1a = __ldcs(r1 + lane); u1b = __ldcs(r1 + lane + 32);
        q0 = weights[a]; q1 = weights[n1];
    }

    for (int n = a; n < b; n += 2) {
        float4 c0a = u0a, c0b = u0b, c1a = u1a, c1b = u1b;
        float p0 = q0, p1 = q1;
        bool has2 = (n + 1 < b);

        int nn = n + 2;
        if (nn < b) {   // prefetch next pair (streaming: x is read exactly once)
            int n1 = (nn + 1 < b) ? nn + 1 : nn;
            const float4* r0 = (const float4*)(x + (size_t)nn * D);
            const float4* r1 = (const float4*)(x + (size_t)n1 * D);
            u0a = __ldcs(r0 + lane); u0b = __ldcs(r0 + lane + 32);
            u1a = __ldcs(r1 + lane); u1b = __ldcs(r1 + lane + 32);
            q0 = weights[nn]; q1 = weights[n1];
        }

        float s0 = c0a.x * w1.x + c0a.y * w1.y + c0a.z * w1.z + c0a.w * w1.w
                 + c0b.x * w2.x + c0b.y * w2.y + c0b.z * w2.z + c0b.w * w2.w;
        float s1 = c1a.x * w1.x + c1a.y * w1.y + c1a.z * w1.z + c1a.w * w1.w
                 + c1b.x * w2.x + c1b.y * w2.y + c1b.z * w2.z + c1b.w * w2.w;
        #pragma unroll
        for (int o = 16; o > 0; o >>= 1) {   // two independent chains, pipelined
            s0 += __shfl_xor_sync(0xffffffffu, s0, o);
            s1 += __shfl_xor_sync(0xffffffffu, s1, o);
        }

        float h0 = fmaf(pv, __logf(p0), s0 + bgv);
        float h1 = has2 ? fmaf(pv, __logf(p1), s1 + bgv) : -FLT_MAX;
        float hm = fmaxf(h0, h1);
        if (hm > m) {                         // warp-uniform
            float r = __expf(m - hm);         // first iter: exp(-inf) = 0
            m = hm; d *= r;
            A1.x *= r; A1.y *= r; A1.z *= r; A1.w *= r;
            A2.x *= r; A2.y *= r; A2.z *= r; A2.w *= r;
        }
        float e0 = __expf(h0 - m);
        float e1 = __expf(h1 - m);            // h1=-FLT_MAX -> 0 when !has2
        d += e0 + e1;
        A1.x = fmaf(e1, c1a.x, fmaf(e0, c0a.x, A1.x));
        A1.y = fmaf(e1, c1a.y, fmaf(e0, c0a.y, A1.y));
        A1.z = fmaf(e1, c1a.z, fmaf(e0, c0a.z, A1.z));
        A1.w = fmaf(e1, c1a.w, fmaf(e0, c0a.w, A1.w));
        A2.x = fmaf(e1, c1b.x, fmaf(e0, c0b.x, A2.x));
        A2.y = fmaf(e1, c1b.y, fmaf(e0, c0b.y, A2.y));
        A2.z = fmaf(e1, c1b.z, fmaf(e0, c0b.z, A2.z));
        A2.w = fmaf(e1, c1b.w, fmaf(e0, c0b.w, A2.w));
    }

    float inv = 1.f / (d + 1e-10f);
    A1.x *= inv; A1.y *= inv; A1.z *= inv; A1.w *= inv;
    A2.x *= inv; A2.y *= inv; A2.z *= inv; A2.w *= inv;
    float4* po = (float4*)(g_pooled + (size_t)seg * D);
    po[lane] = A1; po[lane + 32] = A2;
    if (lane == 0) g_sumg[seg] = d * inv;
}

// --- Kernel 3: out = pooled_norm @ Wm + sumg * bm, packed fma.rn.f32x2 ---
// 256 threads = 256 output columns; GTM=64 rows; acc pairs in 64-bit regs.
// LDS.128 loads land in aligned reg pairs -> zero-cost .b64 operands.
__global__ __launch_bounds__(256) void gemm_kernel(
    const float* __restrict__ Wm, const float* __restrict__ bm,
    float* __restrict__ out, int S)
{
    __shared__ float As[32][GTM + 4];    // +4 keeps 16B row alignment
    int tid = threadIdx.x;
    int row0 = blockIdx.x * GTM;

    unsigned long long acc2[GTM / 2];
    #pragma unroll
    for (int i = 0; i < GTM / 2; i++) acc2[i] = 0ull;

    for (int k0 = 0; k0 < D; k0 += 32) {
        #pragma unroll
        for (int i = 0; i < GTM * 32 / 256; i++) {
            int idx = tid + i * 256;
            int r = idx >> 5, kk = idx & 31;
            int row = row0 + r;
            As[kk][r] = (row < S) ? g_pooled[(size_t)row * D + k0 + kk] : 0.f;
        }
        __syncthreads();
        #pragma unroll
        for (int kk = 0; kk < 32; kk++) {
            float bv = Wm[(size_t)(k0 + kk) * D + tid];
            unsigned long long b2;
            asm("mov.b64 %0, {%1, %1};" : "=l"(b2) : "r"(__float_as_uint(bv)));
            #pragma unroll
            for (int r4 = 0; r4 < GTM; r4 += 4) {
                double2 dv = *(const double2*)&As[kk][r4];
                unsigned long long a01 = __double_as_longlong(dv.x);
                unsigned long long a23 = __double_as_longlong(dv.y);
                asm("fma.rn.f32x2 %0, %1, %2, %0;" : "+l"(acc2[r4 / 2])     : "l"(a01), "l"(b2));
                asm("fma.rn.f32x2 %0, %1, %2, %0;" : "+l"(acc2[r4 / 2 + 1]) : "l"(a23), "l"(b2));
            }
        }
        __syncthreads();
    }

    float bmv = bm[tid];
    #pragma unroll
    for (int r = 0; r < GTM; r += 2) {
        unsigned long long v = acc2[r / 2];
        float lo = __uint_as_float((unsigned)v);          // element 0 = low word = row r
        float hi = __uint_as_float((unsigned)(v >> 32));  // row r+1
        int row = row0 + r;
        if (row < S)     out[(size_t)row * D + tid]       = lo + g_sumg[row] * bmv;
        if (row + 1 < S) out[(size_t)(row + 1) * D + tid] = hi + g_sumg[row + 1] * bmv;
    }
}

extern "C" void kernel_launch(void* const* d_in, const int* in_sizes, int n_in,
                              void* d_out, int out_size) {
    const float* x       = (const float*)d_in[0];
    const float* weights = (const float*)d_in[1];
    const float* Wg      = (const float*)d_in[2];
    const float* bg      = (const float*)d_in[3];
    const float* Wm      = (const float*)d_in[4];
    const float* bm      = (const float*)d_in[5];
    const float* p       = (const float*)d_in[6];
    const int*   index   = (const int*)d_in[7];
    float* out = (float*)d_out;

    int N = in_sizes[7];
    int S = out_size / D;

    segstart_kernel<<<(N + 255) / 256, 256>>>(index, N, S);
    fused_kernel<<<(S * 32 + 255) / 256, 256>>>(x, weights, Wg, bg, p, S);
    gemm_kernel<<<(S + GTM - 1) / GTM, 256>>>(Wm, bm, out, S);
}